// round 12
// baseline (speedup 1.0000x reference)
#include <cuda_runtime.h>
#include <cuda_fp16.h>
#include <cstdint>

// ---------------- problem constants ----------------
#define NNODES 50000
#define NGENE  40000
#define NGO    10000
#define NEDGES 800000
#define DIM    512
#define HID2D  256
#define GOIDD  4096
#define MPAD_GO 10112   // 79*128
#define MPAD_N  50048   // 391*128
#define NROWS_BOT 39936 // 312*128
#define NROWS_TOP 10112 // 79*128
#define NSCANB 196      // ceil(50000/256)
#define NCHUNK 4
// chunk boundaries for the gather1/layer2 pipeline (128-aligned except final)
__constant__ int c_cb[NCHUNK + 1] = {0, 12544, 25088, 37632, 50000};
static const int h_cb[NCHUNK + 1] = {0, 12544, 25088, 37632, 50000};

// ---------------- helpers ----------------
__device__ __forceinline__ uint32_t smem_u32(const void* p) {
    uint32_t a;
    asm("{ .reg .u64 t; cvta.to.shared.u64 t, %1; cvt.u32.u64 %0, t; }" : "=r"(a) : "l"(p));
    return a;
}
__device__ __forceinline__ void cp16(uint32_t d, const void* s) {
    asm volatile("cp.async.cg.shared.global [%0], [%1], 16;" :: "r"(d), "l"(s) : "memory");
}
#define CP_COMMIT() asm volatile("cp.async.commit_group;" ::: "memory")
#define CP_WAIT(n)  asm volatile("cp.async.wait_group %0;" :: "n"(n) : "memory")

__device__ __forceinline__ void ldsm4(uint32_t* r, uint32_t addr) {
    asm volatile("ldmatrix.sync.aligned.m8n8.x4.shared.b16 {%0,%1,%2,%3}, [%4];"
        : "=r"(r[0]), "=r"(r[1]), "=r"(r[2]), "=r"(r[3]) : "r"(addr));
}
__device__ __forceinline__ void mma16816(float* d, const uint32_t* a, const uint32_t* b) {
    asm volatile(
        "mma.sync.aligned.m16n8k16.row.col.f32.f16.f16.f32 "
        "{%0,%1,%2,%3}, {%4,%5,%6,%7}, {%8,%9}, {%0,%1,%2,%3};"
        : "+f"(d[0]), "+f"(d[1]), "+f"(d[2]), "+f"(d[3])
        : "r"(a[0]), "r"(a[1]), "r"(a[2]), "r"(a[3]), "r"(b[0]), "r"(b[1]));
}
__device__ __forceinline__ uint32_t swz(uint32_t base, uint32_t off) {
    return base + (off ^ ((off >> 3) & 0x70));
}
__device__ __forceinline__ void acc8(float* a, uint4 r, float w) {
    float2 f;
    f = __half22float2(*(const __half2*)&r.x); a[0] += w * f.x; a[1] += w * f.y;
    f = __half22float2(*(const __half2*)&r.y); a[2] += w * f.x; a[3] += w * f.y;
    f = __half22float2(*(const __half2*)&r.z); a[4] += w * f.x; a[5] += w * f.y;
    f = __half22float2(*(const __half2*)&r.w); a[6] += w * f.x; a[7] += w * f.y;
}
__device__ __forceinline__ void unpack8(float* o, uint4 r) {
    float2 f;
    f = __half22float2(*(const __half2*)&r.x); o[0] = f.x; o[1] = f.y;
    f = __half22float2(*(const __half2*)&r.y); o[2] = f.x; o[3] = f.y;
    f = __half22float2(*(const __half2*)&r.z); o[4] = f.x; o[5] = f.y;
    f = __half22float2(*(const __half2*)&r.w); o[6] = f.x; o[7] = f.y;
}

// ---------------- scratch (device globals) ----------------
__device__ int   g_is64;
__device__ int   g_src[NEDGES];
__device__ int   g_dst[NEDGES];
__device__ int   g_indeg[NNODES];
__device__ int   g_rowptr[NNODES + 1];
__device__ int   g_cursor[NNODES];
__device__ int   g_bsum[256];
__device__ float g_dinv[NNODES];
__device__ __align__(128) int   g_csr_src[NEDGES];
__device__ __align__(128) float g_csr_w[NEDGES];

__device__ __align__(128) __half g_hw16[(size_t)NNODES * DIM];   // layer1 conv messages
__device__ __align__(128) __half g_hw2 [(size_t)NNODES * HID2D]; // layer2 conv messages
__device__ __align__(128) float g_r1[(size_t)NNODES * DIM];
__device__ __align__(128) float g_r2[(size_t)NNODES * HID2D];

__device__ __align__(128) __half g_xgo[(size_t)MPAD_GO * GOIDD];
__device__ __align__(128) __half g_go1[(size_t)MPAD_GO * 1024];
__device__ __align__(128) __half g_xt [(size_t)MPAD_N * DIM];
__device__ __align__(128) __half g_h1 [(size_t)MPAD_N * DIM];

__device__ __align__(128) __half g_Wgo1T[1024 * 4096];
__device__ __align__(128) __half g_Wgo2T[512 * 1024];
__device__ __align__(128) __half g_W1T[1024 * 512];   // [Wc1T ; Wr1T]
__device__ __align__(128) __half g_W2T[512 * 512];    // [Wc2T ; Wr2T]

// ---------------- graph preprocessing ----------------
__global__ void k_init_indeg() {
    int i = blockIdx.x * blockDim.x + threadIdx.x;
    if (i < NNODES) g_indeg[i] = 0;
}
__global__ void k_detect_idx_dtype(const int* __restrict__ raw) {
    __shared__ int flag;
    if (threadIdx.x == 0) flag = 1;
    __syncthreads();
    if (raw[2 * threadIdx.x + 1] != 0) flag = 0;
    __syncthreads();
    if (threadIdx.x == 0) g_is64 = flag;
}
__global__ void k_convert_edges(const int* __restrict__ raw) {
    int e = blockIdx.x * blockDim.x + threadIdx.x;
    if (e >= NEDGES) return;
    int s, d;
    if (g_is64) {
        const long long* r64 = (const long long*)raw;
        s = (int)r64[e]; d = (int)r64[NEDGES + e];
    } else {
        s = raw[e]; d = raw[NEDGES + e];
    }
    g_src[e] = s; g_dst[e] = d;
    atomicAdd(&g_indeg[d], 1);
}
__global__ void k_dinv() {
    int i = blockIdx.x * blockDim.x + threadIdx.x;
    if (i < NNODES) g_dinv[i] = rsqrtf(1.0f + (float)g_indeg[i]);
}
__global__ void k_scan1() {
    __shared__ int sh[256];
    const int b = blockIdx.x, t = threadIdx.x;
    const int i = b * 256 + t;
    int v = (i < NNODES) ? g_indeg[i] : 0;
    sh[t] = v;
    __syncthreads();
#pragma unroll
    for (int off = 1; off < 256; off <<= 1) {
        int x = (t >= off) ? sh[t - off] : 0;
        __syncthreads();
        sh[t] += x;
        __syncthreads();
    }
    if (i < NNODES) g_rowptr[i] = sh[t] - v;
    if (t == 255) g_bsum[b] = sh[255];
}
__global__ void k_scan2() {
    __shared__ int sh[256];
    const int t = threadIdx.x;
    int v = (t < NSCANB) ? g_bsum[t] : 0;
    sh[t] = v;
    __syncthreads();
#pragma unroll
    for (int off = 1; off < 256; off <<= 1) {
        int x = (t >= off) ? sh[t - off] : 0;
        __syncthreads();
        sh[t] += x;
        __syncthreads();
    }
    if (t < NSCANB) g_bsum[t] = sh[t] - v;
    if (t == 255) g_rowptr[NNODES] = sh[255];
}
__global__ void k_scan3() {
    const int b = blockIdx.x, t = threadIdx.x;
    const int i = b * 256 + t;
    if (i < NNODES) {
        int r = g_rowptr[i] + g_bsum[b];
        g_rowptr[i] = r;
        g_cursor[i] = r;
    }
}
__global__ void k_fill_csr() {
    int e = blockIdx.x * blockDim.x + threadIdx.x;
    if (e >= NEDGES) return;
    int s = g_src[e], d = g_dst[e];
    int p = atomicAdd(&g_cursor[d], 1);
    g_csr_src[p] = s;
    g_csr_w[p]   = g_dinv[s] * g_dinv[d];
}

// ---------------- conversion kernels ----------------
__global__ void k_cvt_xgo(const float* __restrict__ x) {
    size_t i = (size_t)blockIdx.x * blockDim.x + threadIdx.x;
    const size_t total = (size_t)MPAD_GO * GOIDD / 2;
    if (i >= total) return;
    size_t row = i / (GOIDD / 2), c2 = i % (GOIDD / 2);
    float2 v = make_float2(0.f, 0.f);
    if (row < NGO) v = ((const float2*)x)[((size_t)(NGENE + row) * GOIDD) / 2 + c2];
    ((__half2*)g_xgo)[i] = __floats2half2_rn(v.x, v.y);
}
__global__ void k_cvt_gene(const float* __restrict__ x) {
    size_t i = (size_t)blockIdx.x * blockDim.x + threadIdx.x;
    const size_t total = (size_t)NGENE * DIM / 2;
    if (i >= total) return;
    size_t row = i / (DIM / 2), c2 = i % (DIM / 2);
    float2 v = ((const float2*)x)[((size_t)row * GOIDD) / 2 + c2];
    ((__half2*)g_xt)[(size_t)row * (DIM / 2) + c2] = __floats2half2_rn(v.x, v.y);
}
__global__ void k_cvt_wT(const float* __restrict__ W, __half* __restrict__ dh,
                         int K, int N) {
    __shared__ float tile[32][33];
    const int nb = blockIdx.x * 32, kb = blockIdx.y * 32;
    const int tx = threadIdx.x, ty = threadIdx.y;
#pragma unroll
    for (int r = 0; r < 32; r += 8)
        tile[ty + r][tx] = W[(size_t)(kb + ty + r) * N + nb + tx];
    __syncthreads();
#pragma unroll
    for (int r = 0; r < 32; r += 8) {
        float v = tile[tx][ty + r];
        dh[(size_t)(nb + ty + r) * K + kb + tx] = __float2half_rn(v);
    }
}
__global__ void k_zero16(__half* p, int n2) {
    int i = blockIdx.x * blockDim.x + threadIdx.x;
    if (i < n2) ((uint32_t*)p)[i] = 0u;
}

// ---------------- fp16 HMMA GEMM ----------------
#define GEMM_SMEM (3 * 2 * 16384)   // 96 KB

template <bool DUAL, bool BIAS, bool RELU>
__global__ __launch_bounds__(256, 2)
void k_hgemm(const __half* __restrict__ A, const __half* __restrict__ B,
             const float* __restrict__ bias,
             __half* __restrict__ Ch, float* __restrict__ Cr,
             int M, int N, int K)
{
    extern __shared__ char smem[];
    const uint32_t sb = smem_u32(smem);
    const int tid  = threadIdx.x;
    const int wid  = tid >> 5;
    const int lane = tid & 31;
    const int wm   = wid >> 1;
    const int wn   = wid & 1;
    const int bm = blockIdx.y * 128, bn = blockIdx.x * 128;

    const uint32_t STAGE = 2 * 16384;

    const int lrow  = tid >> 1;
    const int lhalf = (tid & 1) * 64;
    const char* srcA = (const char*)(A + (size_t)(bm + lrow) * K) + lhalf;
    const char* srcB = (const char*)(B + (size_t)(bn + lrow) * K) + lhalf;

    const int NC = K / 64;

    auto load_chunk = [&](int s, int c) {
        const uint32_t kb = (uint32_t)c * 128;
        const uint32_t stg = sb + (uint32_t)s * STAGE;
        const uint32_t lbase = (uint32_t)lrow * 128 + (uint32_t)lhalf;
#pragma unroll
        for (int i = 0; i < 4; i++) {
            uint32_t off = lbase + i * 16;
            cp16(swz(stg, off),         srcA + kb + i * 16);
            cp16(swz(stg + 16384, off), srcB + kb + i * 16);
        }
        CP_COMMIT();
    };

    float acc[64];
#pragma unroll
    for (int i = 0; i < 64; i++) acc[i] = 0.f;

    const uint32_t a_row  = (uint32_t)(wm * 32) + (lane & 15);
    const uint32_t a_ksel = (lane >> 4) << 4;
    const uint32_t b_row  = (uint32_t)(wn * 64) + (lane & 7) + ((lane >> 4) << 3);
    const uint32_t b_ksel = (lane & 8) ? 16u : 0u;

    load_chunk(0, 0);
    if (NC > 1) load_chunk(1, 1);

    for (int c = 0; c < NC; c++) {
        if (c + 2 < NC) load_chunk((c + 2) % 3, c + 2);
        if (c + 2 < NC)      { CP_WAIT(2); }
        else if (c + 1 < NC) { CP_WAIT(1); }
        else                 { CP_WAIT(0); }
        __syncthreads();

        const uint32_t stg = sb + (uint32_t)(c % 3) * STAGE;
        const uint32_t tA = stg;
        const uint32_t tB = stg + 16384;

#pragma unroll
        for (int ks = 0; ks < 4; ks++) {
            const uint32_t kb = (uint32_t)ks * 32;
            uint32_t a[8];
            ldsm4(&a[0], swz(tA, (a_row)      * 128 + kb + a_ksel));
            ldsm4(&a[4], swz(tA, (a_row + 16) * 128 + kb + a_ksel));
#pragma unroll
            for (int p = 0; p < 4; p++) {
                uint32_t b4[4];
                ldsm4(b4, swz(tB, (b_row + p * 16) * 128 + kb + b_ksel));
#pragma unroll
                for (int mt = 0; mt < 2; mt++) {
                    mma16816(&acc[(mt * 8 + 2 * p) * 4],     &a[mt * 4], &b4[0]);
                    mma16816(&acc[(mt * 8 + 2 * p + 1) * 4], &a[mt * 4], &b4[2]);
                }
            }
        }
        __syncthreads();
    }

    // ---- epilogue ----
    const int half  = N >> 1;
    const bool sec  = DUAL && (bn >= half);
    const int cbase = sec ? half : 0;
    const int cstr  = DUAL ? half : N;

#pragma unroll
    for (int mt = 0; mt < 2; mt++) {
#pragma unroll
        for (int nt = 0; nt < 8; nt++) {
            const float* d = &acc[(mt * 8 + nt) * 4];
            const int r0 = bm + wm * 32 + mt * 16 + (lane >> 2);
            const int r1 = r0 + 8;
            const int col = bn + wn * 64 + nt * 8 + 2 * (lane & 3);
            float2 v0 = make_float2(d[0], d[1]);
            float2 v1 = make_float2(d[2], d[3]);
            if (DUAL) {
                const int cc = col - cbase;
                if (sec) {
                    if (BIAS) {
                        float b0 = bias[cc], b1 = bias[cc + 1];
                        v0.x += b0; v0.y += b1; v1.x += b0; v1.y += b1;
                    }
                    if (r0 < M) *(float2*)(Cr + (size_t)r0 * cstr + cc) = v0;
                    if (r1 < M) *(float2*)(Cr + (size_t)r1 * cstr + cc) = v1;
                } else {
                    if (r0 < M) *(__half2*)(Ch + (size_t)r0 * cstr + cc) = __floats2half2_rn(v0.x, v0.y);
                    if (r1 < M) *(__half2*)(Ch + (size_t)r1 * cstr + cc) = __floats2half2_rn(v1.x, v1.y);
                }
            } else {
                if (BIAS) {
                    float b0 = bias[col], b1 = bias[col + 1];
                    v0.x += b0; v0.y += b1; v1.x += b0; v1.y += b1;
                }
                if (RELU) {
                    v0.x = fmaxf(v0.x, 0.f); v0.y = fmaxf(v0.y, 0.f);
                    v1.x = fmaxf(v1.x, 0.f); v1.y = fmaxf(v1.y, 0.f);
                }
                if (r0 < M) *(__half2*)(Ch + (size_t)r0 * N + col) = __floats2half2_rn(v0.x, v0.y);
                if (r1 < M) *(__half2*)(Ch + (size_t)r1 * N + col) = __floats2half2_rn(v1.x, v1.y);
            }
        }
    }
}

// ---------------- GCN aggregate + epilogue (CSR gather, fp16 messages) --------
// node id = base + blockIdx.x.
template <int F, bool H16OUT, bool FUSE>
__global__ void k_gather_epi(const __half* __restrict__ hw, const float* __restrict__ rin,
                             const float* __restrict__ bias, __half* __restrict__ oh,
                             float* __restrict__ rout,
                             const float* __restrict__ istj, const float* __restrict__ Wf,
                             const float* __restrict__ bf, float* __restrict__ out,
                             int base)
{
    const int F8 = F / 8;
    const int i = base + blockIdx.x;
    const int t = threadIdx.x;
    const int beg = g_rowptr[i], end = g_rowptr[i + 1];
    const uint4* hw8 = (const uint4*)hw;

    float acc[8];
#pragma unroll
    for (int j = 0; j < 8; j++) acc[j] = 0.f;

    int e = beg;
    for (; e + 1 < end; e += 2) {
        int   s0 = g_csr_src[e],     s1 = g_csr_src[e + 1];
        float w0 = g_csr_w[e],       w1 = g_csr_w[e + 1];
        uint4 ra = hw8[(size_t)s0 * F8 + t];
        uint4 rb = hw8[(size_t)s1 * F8 + t];
        acc8(acc, ra, w0);
        acc8(acc, rb, w1);
    }
    if (e < end) {
        int s0 = g_csr_src[e];
        float w0 = g_csr_w[e];
        acc8(acc, hw8[(size_t)s0 * F8 + t], w0);
    }

    const float dv = g_dinv[i];
    const float sn = dv * dv;
    float sv[8];
    unpack8(sv, hw8[(size_t)i * F8 + t]);
    float bb[8], rr[8];
    *(float4*)&bb[0] = ((const float4*)bias)[2 * t];
    *(float4*)&bb[4] = ((const float4*)bias)[2 * t + 1];
    *(float4*)&rr[0] = ((const float4*)(rin + (size_t)i * F))[2 * t];
    *(float4*)&rr[4] = ((const float4*)(rin + (size_t)i * F))[2 * t + 1];

    float o[8];
#pragma unroll
    for (int j = 0; j < 8; j++)
        o[j] = fmaxf(acc[j] + sn * sv[j] + bb[j], 0.f) + rr[j];

    if (H16OUT) {
        uint4 pk;
        *(__half2*)&pk.x = __floats2half2_rn(o[0], o[1]);
        *(__half2*)&pk.y = __floats2half2_rn(o[2], o[3]);
        *(__half2*)&pk.z = __floats2half2_rn(o[4], o[5]);
        *(__half2*)&pk.w = __floats2half2_rn(o[6], o[7]);
        ((uint4*)(oh + (size_t)i * F))[t] = pk;
    } else if (FUSE) {
        float a0 = 0.f, a1 = 0.f;
#pragma unroll
        for (int j = 0; j < 8; j++) {
            int k = 8 * t + j;
            a0 += o[j] * Wf[2 * k];
            a1 += o[j] * Wf[2 * k + 1];
        }
#pragma unroll
        for (int off = 16; off > 0; off >>= 1) {
            a0 += __shfl_down_sync(0xffffffffu, a0, off);
            a1 += __shfl_down_sync(0xffffffffu, a1, off);
        }
        if (t == 0) {
            float tv = istj[i];
            out[2 * i + 0] = a0 + tv * Wf[2 * F + 0] + bf[0];
            out[2 * i + 1] = a1 + tv * Wf[2 * F + 1] + bf[1];
        }
    } else {
        ((float4*)(rout + (size_t)i * F))[2 * t]     = *(float4*)&o[0];
        ((float4*)(rout + (size_t)i * F))[2 * t + 1] = *(float4*)&o[4];
    }
}

// ---------------- host ----------------
template <typename T>
static inline T* sym(const void* s) {
    void* p = nullptr;
    cudaGetSymbolAddress(&p, s);
    return (T*)p;
}

extern "C" void kernel_launch(void* const* d_in, const int* in_sizes, int n_in,
                              void* d_out, int out_size)
{
    const float* x    = (const float*)d_in[0];
    const int*   eraw = (const int*)  d_in[1];
    const float* istj = (const float*)d_in[2];
    const int base = (in_sizes[3] < 1000) ? 4 : 3;
    const float* W_go1 = (const float*)d_in[base + 0];
    const float* b_go1 = (const float*)d_in[base + 1];
    const float* W_go2 = (const float*)d_in[base + 2];
    const float* b_go2 = (const float*)d_in[base + 3];
    const float* W_c1  = (const float*)d_in[base + 4];
    const float* b_c1  = (const float*)d_in[base + 5];
    const float* W_c2  = (const float*)d_in[base + 6];
    const float* b_c2  = (const float*)d_in[base + 7];
    const float* W_r1  = (const float*)d_in[base + 8];
    const float* b_r1  = (const float*)d_in[base + 9];
    const float* W_r2  = (const float*)d_in[base + 10];
    const float* b_r2  = (const float*)d_in[base + 11];
    const float* W_f   = (const float*)d_in[base + 12];
    const float* b_f   = (const float*)d_in[base + 13];
    float* out = (float*)d_out;

    static cudaStream_t sA = nullptr, sB = nullptr;
    static cudaEvent_t eFork = nullptr, eGene = nullptr, eTop = nullptr, eJoin = nullptr;
    static cudaEvent_t eG[NCHUNK] = {nullptr, nullptr, nullptr, nullptr};
    static cudaEvent_t eL2 = nullptr;
    if (!sA) {
        cudaStreamCreateWithFlags(&sA, cudaStreamNonBlocking);
        cudaStreamCreateWithFlags(&sB, cudaStreamNonBlocking);
        cudaEventCreateWithFlags(&eFork, cudaEventDisableTiming);
        cudaEventCreateWithFlags(&eGene, cudaEventDisableTiming);
        cudaEventCreateWithFlags(&eTop,  cudaEventDisableTiming);
        cudaEventCreateWithFlags(&eJoin, cudaEventDisableTiming);
        cudaEventCreateWithFlags(&eL2,   cudaEventDisableTiming);
        for (int j = 0; j < NCHUNK; j++)
            cudaEventCreateWithFlags(&eG[j], cudaEventDisableTiming);
        cudaFuncSetAttribute((const void*)k_hgemm<false, true, true >,
                             cudaFuncAttributeMaxDynamicSharedMemorySize, GEMM_SMEM);
        cudaFuncSetAttribute((const void*)k_hgemm<true,  true, false>,
                             cudaFuncAttributeMaxDynamicSharedMemorySize, GEMM_SMEM);
    }

    __half* hw16 = sym<__half>(g_hw16);
    __half* hw2  = sym<__half>(g_hw2);
    float* p_r1 = sym<float>(g_r1);
    float* p_r2 = sym<float>(g_r2);
    __half* xgo  = sym<__half>(g_xgo);
    __half* go1  = sym<__half>(g_go1);
    __half* xt   = sym<__half>(g_xt);
    __half* h1   = sym<__half>(g_h1);
    __half* wgo1 = sym<__half>(g_Wgo1T);
    __half* wgo2 = sym<__half>(g_Wgo2T);
    __half* w1   = sym<__half>(g_W1T);
    __half* w2   = sym<__half>(g_W2T);

    // ---- fork ----
    cudaEventRecord(eFork, 0);
    cudaStreamWaitEvent(sA, eFork, 0);
    cudaStreamWaitEvent(sB, eFork, 0);

    // ======== stream B: goid MLP chain + layer1-top ========
    {
        dim3 b(32, 8);
        k_cvt_wT<<<dim3(1024 / 32, 4096 / 32), b, 0, sB>>>(W_go1, wgo1, 4096, 1024);
        k_cvt_wT<<<dim3(512 / 32, 1024 / 32),  b, 0, sB>>>(W_go2, wgo2, 1024, 512);
    }
    {
        size_t n2 = (size_t)MPAD_GO * GOIDD / 2;
        k_cvt_xgo<<<(unsigned)((n2 + 255) / 256), 256, 0, sB>>>(x);
    }
    k_zero16<<<(112 * 1024 / 2 + 255) / 256, 256, 0, sB>>>(go1 + (size_t)NGO * 1024, 112 * 1024 / 2);
    {
        dim3 g(1024 / 128, MPAD_GO / 128);
        k_hgemm<false, true, true><<<g, 256, GEMM_SMEM, sB>>>(
            xgo, wgo1, b_go1, go1, nullptr, NGO, 1024, 4096);
    }
    {
        dim3 g(512 / 128, MPAD_GO / 128);
        k_hgemm<false, true, true><<<g, 256, GEMM_SMEM, sB>>>(
            go1, wgo2, b_go2, xt + (size_t)NGENE * DIM, nullptr, NGO, 512, 1024);
    }

    // ======== stream A: graph preproc + gene conversion + layer1-bottom ========
    k_init_indeg<<<(NNODES + 255) / 256, 256, 0, sA>>>();
    k_detect_idx_dtype<<<1, 1024, 0, sA>>>(eraw);
    k_convert_edges<<<(NEDGES + 255) / 256, 256, 0, sA>>>(eraw);
    k_dinv<<<(NNODES + 255) / 256, 256, 0, sA>>>();
    k_scan1<<<NSCANB, 256, 0, sA>>>();
    k_scan2<<<1, 256, 0, sA>>>();
    k_scan3<<<NSCANB, 256, 0, sA>>>();
    k_fill_csr<<<(NEDGES + 255) / 256, 256, 0, sA>>>();
    k_cvt_gene<<<(unsigned)(((size_t)NGENE * DIM / 2 + 255) / 256), 256, 0, sA>>>(x);
    {
        dim3 b(32, 8);
        k_cvt_wT<<<dim3(512 / 32, 512 / 32), b, 0, sA>>>(W_c1, w1,             512, 512);
        k_cvt_wT<<<dim3(512 / 32, 512 / 32), b, 0, sA>>>(W_r1, w1 + 512 * 512, 512, 512);
        k_cvt_wT<<<dim3(256 / 32, 512 / 32), b, 0, sA>>>(W_c2, w2,             512, 256);
        k_cvt_wT<<<dim3(256 / 32, 512 / 32), b, 0, sA>>>(W_r2, w2 + 256 * 512, 512, 256);
    }
    k_zero16<<<(48 * 512 / 2 + 255) / 256, 256, 0, sA>>>(xt + (size_t)NNODES * DIM, 48 * 512 / 2);
    k_zero16<<<(48 * 512 / 2 + 255) / 256, 256, 0, sA>>>(h1 + (size_t)NNODES * DIM, 48 * 512 / 2);
    cudaEventRecord(eGene, sA);

    // layer1-bottom: rows [0, 39936)
    {
        dim3 g(1024 / 128, NROWS_BOT / 128);
        k_hgemm<true, true, false><<<g, 256, GEMM_SMEM, sA>>>(
            xt, w1, b_r1, hw16, p_r1, NROWS_BOT, 1024, 512);
    }

    // layer1-top on stream B
    cudaStreamWaitEvent(sB, eGene, 0);
    {
        dim3 g(1024 / 128, NROWS_TOP / 128);
        k_hgemm<true, true, false><<<g, 256, GEMM_SMEM, sB>>>(
            xt   + (size_t)NROWS_BOT * DIM,
            w1, b_r1,
            hw16 + (size_t)NROWS_BOT * DIM,
            p_r1 + (size_t)NROWS_BOT * DIM,
            NNODES - NROWS_BOT, 1024, 512);
    }
    cudaEventRecord(eTop, sB);

    // ======== pipelined tail: gather1 chunks (sA) || layer2 chunks (sB) ========
    cudaStreamWaitEvent(sA, eTop, 0);
    for (int j = 0; j < NCHUNK; j++) {
        const int b0 = h_cb[j], b1 = h_cb[j + 1];
        k_gather_epi<DIM, true, false><<<b1 - b0, DIM / 8, 0, sA>>>(
            hw16, p_r1, b_c1, h1, nullptr, nullptr, nullptr, nullptr, nullptr, b0);
        cudaEventRecord(eG[j], sA);
        cudaStreamWaitEvent(sB, eG[j], 0);
        const int m = b1 - b0;                 // rows this chunk
        const int tiles = (m + 127) / 128;     // h1 rows padded/zeroed to MPAD_N
        dim3 g(512 / 128, tiles);
        k_hgemm<true, true, false><<<g, 256, GEMM_SMEM, sB>>>(
            h1   + (size_t)b0 * DIM,
            w2, b_r2,
            hw2  + (size_t)b0 * HID2D,
            p_r2 + (size_t)b0 * HID2D,
            m, 512, 512);
    }
    cudaEventRecord(eL2, sB);

    // gather2 fused with fusion head, gene nodes only
    cudaStreamWaitEvent(sA, eL2, 0);
    k_gather_epi<HID2D, false, true><<<NGENE, HID2D / 8, 0, sA>>>(
        hw2, p_r2, b_c2, nullptr, nullptr, istj, W_f, b_f, out, 0);

    // ---- join ----
    cudaEventRecord(eJoin, sA);
    cudaStreamWaitEvent(0, eJoin, 0);

    (void)n_in; (void)out_size;
}

// round 13
// speedup vs baseline: 1.5229x; 1.5229x over previous
#include <cuda_runtime.h>
#include <cuda_fp16.h>
#include <cstdint>

// ---------------- problem constants ----------------
#define NNODES 50000
#define NGENE  40000
#define NGO    10000
#define NEDGES 800000
#define DIM    512
#define HID2D  256
#define GOIDD  4096
#define MPAD_GO 10112   // 79*128
#define MPAD_N  50048   // 391*128
#define NROWS_BOT 39936 // 312*128 (gene-only rows of layer1)
#define NROWS_TOP 10112 // 79*128
#define NSCANB 196      // ceil(50000/256)

// ---------------- helpers ----------------
__device__ __forceinline__ uint32_t smem_u32(const void* p) {
    uint32_t a;
    asm("{ .reg .u64 t; cvta.to.shared.u64 t, %1; cvt.u32.u64 %0, t; }" : "=r"(a) : "l"(p));
    return a;
}
__device__ __forceinline__ void cp16(uint32_t d, const void* s) {
    asm volatile("cp.async.cg.shared.global [%0], [%1], 16;" :: "r"(d), "l"(s) : "memory");
}
#define CP_COMMIT() asm volatile("cp.async.commit_group;" ::: "memory")
#define CP_WAIT(n)  asm volatile("cp.async.wait_group %0;" :: "n"(n) : "memory")

__device__ __forceinline__ void ldsm4(uint32_t* r, uint32_t addr) {
    asm volatile("ldmatrix.sync.aligned.m8n8.x4.shared.b16 {%0,%1,%2,%3}, [%4];"
        : "=r"(r[0]), "=r"(r[1]), "=r"(r[2]), "=r"(r[3]) : "r"(addr));
}
__device__ __forceinline__ void mma16816(float* d, const uint32_t* a, const uint32_t* b) {
    asm volatile(
        "mma.sync.aligned.m16n8k16.row.col.f32.f16.f16.f32 "
        "{%0,%1,%2,%3}, {%4,%5,%6,%7}, {%8,%9}, {%0,%1,%2,%3};"
        : "+f"(d[0]), "+f"(d[1]), "+f"(d[2]), "+f"(d[3])
        : "r"(a[0]), "r"(a[1]), "r"(a[2]), "r"(a[3]), "r"(b[0]), "r"(b[1]));
}
__device__ __forceinline__ uint32_t swz(uint32_t base, uint32_t off) {
    return base + (off ^ ((off >> 3) & 0x70));
}
// accumulate 8 fp16 features (one uint4) scaled by w
__device__ __forceinline__ void acc8(float* a, uint4 r, float w) {
    float2 f;
    f = __half22float2(*(const __half2*)&r.x); a[0] += w * f.x; a[1] += w * f.y;
    f = __half22float2(*(const __half2*)&r.y); a[2] += w * f.x; a[3] += w * f.y;
    f = __half22float2(*(const __half2*)&r.z); a[4] += w * f.x; a[5] += w * f.y;
    f = __half22float2(*(const __half2*)&r.w); a[6] += w * f.x; a[7] += w * f.y;
}
__device__ __forceinline__ void unpack8(float* o, uint4 r) {
    float2 f;
    f = __half22float2(*(const __half2*)&r.x); o[0] = f.x; o[1] = f.y;
    f = __half22float2(*(const __half2*)&r.y); o[2] = f.x; o[3] = f.y;
    f = __half22float2(*(const __half2*)&r.z); o[4] = f.x; o[5] = f.y;
    f = __half22float2(*(const __half2*)&r.w); o[6] = f.x; o[7] = f.y;
}

// ---------------- scratch (device globals) ----------------
__device__ int   g_is64;
__device__ int   g_src[NEDGES];
__device__ int   g_dst[NEDGES];
__device__ int   g_indeg[NNODES];
__device__ int   g_rowptr[NNODES + 1];
__device__ int   g_cursor[NNODES];
__device__ int   g_bsum[256];
__device__ float g_dinv[NNODES];
__device__ __align__(128) int   g_csr_src[NEDGES];
__device__ __align__(128) float g_csr_w[NEDGES];

__device__ __align__(128) __half g_hw16[(size_t)NNODES * DIM];  // conv messages (fp16)
__device__ __align__(128) float g_r1[(size_t)NNODES * DIM];
__device__ __align__(128) float g_r2[(size_t)NNODES * HID2D];

// fp16 activations (rows padded to 128 multiples)
__device__ __align__(128) __half g_xgo[(size_t)MPAD_GO * GOIDD];
__device__ __align__(128) __half g_go1[(size_t)MPAD_GO * 1024];
__device__ __align__(128) __half g_xt [(size_t)MPAD_N * DIM];
__device__ __align__(128) __half g_h1 [(size_t)MPAD_N * DIM];

// fp16 transposed weights ([N,K] K-major)
__device__ __align__(128) __half g_Wgo1T[1024 * 4096];
__device__ __align__(128) __half g_Wgo2T[512 * 1024];
__device__ __align__(128) __half g_W1T[1024 * 512];   // [Wc1T ; Wr1T]
__device__ __align__(128) __half g_W2T[512 * 512];    // [Wc2T ; Wr2T]

// ---------------- graph preprocessing ----------------
__global__ void k_init_indeg() {
    int i = blockIdx.x * blockDim.x + threadIdx.x;
    if (i < NNODES) g_indeg[i] = 0;
}
__global__ void k_detect_idx_dtype(const int* __restrict__ raw) {
    __shared__ int flag;
    if (threadIdx.x == 0) flag = 1;
    __syncthreads();
    if (raw[2 * threadIdx.x + 1] != 0) flag = 0;
    __syncthreads();
    if (threadIdx.x == 0) g_is64 = flag;
}
__global__ void k_convert_edges(const int* __restrict__ raw) {
    int e = blockIdx.x * blockDim.x + threadIdx.x;
    if (e >= NEDGES) return;
    int s, d;
    if (g_is64) {
        const long long* r64 = (const long long*)raw;
        s = (int)r64[e]; d = (int)r64[NEDGES + e];
    } else {
        s = raw[e]; d = raw[NEDGES + e];
    }
    g_src[e] = s; g_dst[e] = d;
    atomicAdd(&g_indeg[d], 1);
}
__global__ void k_dinv() {
    int i = blockIdx.x * blockDim.x + threadIdx.x;
    if (i < NNODES) g_dinv[i] = rsqrtf(1.0f + (float)g_indeg[i]);
}
__global__ void k_scan1() {
    __shared__ int sh[256];
    const int b = blockIdx.x, t = threadIdx.x;
    const int i = b * 256 + t;
    int v = (i < NNODES) ? g_indeg[i] : 0;
    sh[t] = v;
    __syncthreads();
#pragma unroll
    for (int off = 1; off < 256; off <<= 1) {
        int x = (t >= off) ? sh[t - off] : 0;
        __syncthreads();
        sh[t] += x;
        __syncthreads();
    }
    if (i < NNODES) g_rowptr[i] = sh[t] - v;
    if (t == 255) g_bsum[b] = sh[255];
}
__global__ void k_scan2() {
    __shared__ int sh[256];
    const int t = threadIdx.x;
    int v = (t < NSCANB) ? g_bsum[t] : 0;
    sh[t] = v;
    __syncthreads();
#pragma unroll
    for (int off = 1; off < 256; off <<= 1) {
        int x = (t >= off) ? sh[t - off] : 0;
        __syncthreads();
        sh[t] += x;
        __syncthreads();
    }
    if (t < NSCANB) g_bsum[t] = sh[t] - v;
    if (t == 255) g_rowptr[NNODES] = sh[255];
}
__global__ void k_scan3() {
    const int b = blockIdx.x, t = threadIdx.x;
    const int i = b * 256 + t;
    if (i < NNODES) {
        int r = g_rowptr[i] + g_bsum[b];
        g_rowptr[i] = r;
        g_cursor[i] = r;
    }
}
__global__ void k_fill_csr() {
    int e = blockIdx.x * blockDim.x + threadIdx.x;
    if (e >= NEDGES) return;
    int s = g_src[e], d = g_dst[e];
    int p = atomicAdd(&g_cursor[d], 1);
    g_csr_src[p] = s;
    g_csr_w[p]   = g_dinv[s] * g_dinv[d];
}

// ---------------- conversion kernels ----------------
__global__ void k_cvt_xgo(const float* __restrict__ x) {
    size_t i = (size_t)blockIdx.x * blockDim.x + threadIdx.x;  // half2 unit
    const size_t total = (size_t)MPAD_GO * GOIDD / 2;
    if (i >= total) return;
    size_t row = i / (GOIDD / 2), c2 = i % (GOIDD / 2);
    float2 v = make_float2(0.f, 0.f);
    if (row < NGO) v = ((const float2*)x)[((size_t)(NGENE + row) * GOIDD) / 2 + c2];
    ((__half2*)g_xgo)[i] = __floats2half2_rn(v.x, v.y);
}
__global__ void k_cvt_gene(const float* __restrict__ x) {
    size_t i = (size_t)blockIdx.x * blockDim.x + threadIdx.x;  // half2 unit
    const size_t total = (size_t)NGENE * DIM / 2;
    if (i >= total) return;
    size_t row = i / (DIM / 2), c2 = i % (DIM / 2);
    float2 v = ((const float2*)x)[((size_t)row * GOIDD) / 2 + c2];
    ((__half2*)g_xt)[(size_t)row * (DIM / 2) + c2] = __floats2half2_rn(v.x, v.y);
}
__global__ void k_cvt_wT(const float* __restrict__ W, __half* __restrict__ dh,
                         int K, int N) {
    __shared__ float tile[32][33];
    const int nb = blockIdx.x * 32, kb = blockIdx.y * 32;
    const int tx = threadIdx.x, ty = threadIdx.y;
#pragma unroll
    for (int r = 0; r < 32; r += 8)
        tile[ty + r][tx] = W[(size_t)(kb + ty + r) * N + nb + tx];
    __syncthreads();
#pragma unroll
    for (int r = 0; r < 32; r += 8) {
        float v = tile[tx][ty + r];
        dh[(size_t)(nb + ty + r) * K + kb + tx] = __float2half_rn(v);
    }
}
__global__ void k_zero16(__half* p, int n2) {
    int i = blockIdx.x * blockDim.x + threadIdx.x;
    if (i < n2) ((uint32_t*)p)[i] = 0u;
}

// ---------------- fp16 HMMA GEMM (single weight product) ----------------
#define GEMM_SMEM (3 * 2 * 16384)   // 96 KB

template <bool DUAL, bool BIAS, bool RELU>
__global__ __launch_bounds__(256, 2)
void k_hgemm(const __half* __restrict__ A, const __half* __restrict__ B,
             const float* __restrict__ bias,
             __half* __restrict__ Ch, float* __restrict__ Cr,
             int M, int N, int K)
{
    extern __shared__ char smem[];
    const uint32_t sb = smem_u32(smem);
    const int tid  = threadIdx.x;
    const int wid  = tid >> 5;
    const int lane = tid & 31;
    const int wm   = wid >> 1;
    const int wn   = wid & 1;
    const int bm = blockIdx.y * 128, bn = blockIdx.x * 128;

    const uint32_t STAGE = 2 * 16384;

    const int lrow  = tid >> 1;
    const int lhalf = (tid & 1) * 64;
    const char* srcA = (const char*)(A + (size_t)(bm + lrow) * K) + lhalf;
    const char* srcB = (const char*)(B + (size_t)(bn + lrow) * K) + lhalf;

    const int NC = K / 64;

    auto load_chunk = [&](int s, int c) {
        const uint32_t kb = (uint32_t)c * 128;
        const uint32_t stg = sb + (uint32_t)s * STAGE;
        const uint32_t lbase = (uint32_t)lrow * 128 + (uint32_t)lhalf;
#pragma unroll
        for (int i = 0; i < 4; i++) {
            uint32_t off = lbase + i * 16;
            cp16(swz(stg, off),         srcA + kb + i * 16);
            cp16(swz(stg + 16384, off), srcB + kb + i * 16);
        }
        CP_COMMIT();
    };

    float acc[64];
#pragma unroll
    for (int i = 0; i < 64; i++) acc[i] = 0.f;

    const uint32_t a_row  = (uint32_t)(wm * 32) + (lane & 15);
    const uint32_t a_ksel = (lane >> 4) << 4;
    const uint32_t b_row  = (uint32_t)(wn * 64) + (lane & 7) + ((lane >> 4) << 3);
    const uint32_t b_ksel = (lane & 8) ? 16u : 0u;

    load_chunk(0, 0);
    if (NC > 1) load_chunk(1, 1);

    for (int c = 0; c < NC; c++) {
        if (c + 2 < NC) load_chunk((c + 2) % 3, c + 2);
        if (c + 2 < NC)      { CP_WAIT(2); }
        else if (c + 1 < NC) { CP_WAIT(1); }
        else                 { CP_WAIT(0); }
        __syncthreads();

        const uint32_t stg = sb + (uint32_t)(c % 3) * STAGE;
        const uint32_t tA = stg;
        const uint32_t tB = stg + 16384;

#pragma unroll
        for (int ks = 0; ks < 4; ks++) {
            const uint32_t kb = (uint32_t)ks * 32;
            uint32_t a[8];
            ldsm4(&a[0], swz(tA, (a_row)      * 128 + kb + a_ksel));
            ldsm4(&a[4], swz(tA, (a_row + 16) * 128 + kb + a_ksel));
#pragma unroll
            for (int p = 0; p < 4; p++) {
                uint32_t b4[4];
                ldsm4(b4, swz(tB, (b_row + p * 16) * 128 + kb + b_ksel));
#pragma unroll
                for (int mt = 0; mt < 2; mt++) {
                    mma16816(&acc[(mt * 8 + 2 * p) * 4],     &a[mt * 4], &b4[0]);
                    mma16816(&acc[(mt * 8 + 2 * p + 1) * 4], &a[mt * 4], &b4[2]);
                }
            }
        }
        __syncthreads();
    }

    // ---- epilogue ----
    const int half  = N >> 1;
    const bool sec  = DUAL && (bn >= half);
    const int cbase = sec ? half : 0;
    const int cstr  = DUAL ? half : N;

#pragma unroll
    for (int mt = 0; mt < 2; mt++) {
#pragma unroll
        for (int nt = 0; nt < 8; nt++) {
            const float* d = &acc[(mt * 8 + nt) * 4];
            const int r0 = bm + wm * 32 + mt * 16 + (lane >> 2);
            const int r1 = r0 + 8;
            const int col = bn + wn * 64 + nt * 8 + 2 * (lane & 3);
            float2 v0 = make_float2(d[0], d[1]);
            float2 v1 = make_float2(d[2], d[3]);
            if (DUAL) {
                const int cc = col - cbase;
                if (sec) {
                    if (BIAS) {
                        float b0 = bias[cc], b1 = bias[cc + 1];
                        v0.x += b0; v0.y += b1; v1.x += b0; v1.y += b1;
                    }
                    if (r0 < M) *(float2*)(Cr + (size_t)r0 * cstr + cc) = v0;
                    if (r1 < M) *(float2*)(Cr + (size_t)r1 * cstr + cc) = v1;
                } else {
                    if (r0 < M) *(__half2*)(Ch + (size_t)r0 * cstr + cc) = __floats2half2_rn(v0.x, v0.y);
                    if (r1 < M) *(__half2*)(Ch + (size_t)r1 * cstr + cc) = __floats2half2_rn(v1.x, v1.y);
                }
            } else {
                if (BIAS) {
                    float b0 = bias[col], b1 = bias[col + 1];
                    v0.x += b0; v0.y += b1; v1.x += b0; v1.y += b1;
                }
                if (RELU) {
                    v0.x = fmaxf(v0.x, 0.f); v0.y = fmaxf(v0.y, 0.f);
                    v1.x = fmaxf(v1.x, 0.f); v1.y = fmaxf(v1.y, 0.f);
                }
                if (r0 < M) *(__half2*)(Ch + (size_t)r0 * N + col) = __floats2half2_rn(v0.x, v0.y);
                if (r1 < M) *(__half2*)(Ch + (size_t)r1 * N + col) = __floats2half2_rn(v1.x, v1.y);
            }
        }
    }
}

// ---------------- GCN aggregate + epilogue (CSR gather, fp16 messages) --------
template <int F, bool H16OUT, bool FUSE>
__global__ void k_gather_epi(const __half* __restrict__ hw, const float* __restrict__ rin,
                             const float* __restrict__ bias, __half* __restrict__ oh,
                             float* __restrict__ rout,
                             const float* __restrict__ istj, const float* __restrict__ Wf,
                             const float* __restrict__ bf, float* __restrict__ out)
{
    const int F8 = F / 8;
    const int i = blockIdx.x;
    const int t = threadIdx.x;       // blockDim == F8
    const int beg = g_rowptr[i], end = g_rowptr[i + 1];
    const uint4* hw8 = (const uint4*)hw;

    float acc[8];
#pragma unroll
    for (int j = 0; j < 8; j++) acc[j] = 0.f;

    int e = beg;
    for (; e + 1 < end; e += 2) {
        int   s0 = g_csr_src[e],     s1 = g_csr_src[e + 1];
        float w0 = g_csr_w[e],       w1 = g_csr_w[e + 1];
        uint4 ra = hw8[(size_t)s0 * F8 + t];
        uint4 rb = hw8[(size_t)s1 * F8 + t];
        acc8(acc, ra, w0);
        acc8(acc, rb, w1);
    }
    if (e < end) {
        int s0 = g_csr_src[e];
        float w0 = g_csr_w[e];
        acc8(acc, hw8[(size_t)s0 * F8 + t], w0);
    }

    const float dv = g_dinv[i];
    const float sn = dv * dv;
    float sv[8];
    unpack8(sv, hw8[(size_t)i * F8 + t]);
    float bb[8], rr[8];
    *(float4*)&bb[0] = ((const float4*)bias)[2 * t];
    *(float4*)&bb[4] = ((const float4*)bias)[2 * t + 1];
    *(float4*)&rr[0] = ((const float4*)(rin + (size_t)i * F))[2 * t];
    *(float4*)&rr[4] = ((const float4*)(rin + (size_t)i * F))[2 * t + 1];

    float o[8];
#pragma unroll
    for (int j = 0; j < 8; j++)
        o[j] = fmaxf(acc[j] + sn * sv[j] + bb[j], 0.f) + rr[j];

    if (H16OUT) {
        uint4 pk;
        *(__half2*)&pk.x = __floats2half2_rn(o[0], o[1]);
        *(__half2*)&pk.y = __floats2half2_rn(o[2], o[3]);
        *(__half2*)&pk.z = __floats2half2_rn(o[4], o[5]);
        *(__half2*)&pk.w = __floats2half2_rn(o[6], o[7]);
        ((uint4*)(oh + (size_t)i * F))[t] = pk;
    } else if (FUSE) {
        // blockDim == 32 (one warp). out[i] = o . Wf[:,0/1] + istj*Wf[F] + bf
        float a0 = 0.f, a1 = 0.f;
#pragma unroll
        for (int j = 0; j < 8; j++) {
            int k = 8 * t + j;
            a0 += o[j] * Wf[2 * k];
            a1 += o[j] * Wf[2 * k + 1];
        }
#pragma unroll
        for (int off = 16; off > 0; off >>= 1) {
            a0 += __shfl_down_sync(0xffffffffu, a0, off);
            a1 += __shfl_down_sync(0xffffffffu, a1, off);
        }
        if (t == 0) {
            float tv = istj[i];
            out[2 * i + 0] = a0 + tv * Wf[2 * F + 0] + bf[0];
            out[2 * i + 1] = a1 + tv * Wf[2 * F + 1] + bf[1];
        }
    } else {
        ((float4*)(rout + (size_t)i * F))[2 * t]     = *(float4*)&o[0];
        ((float4*)(rout + (size_t)i * F))[2 * t + 1] = *(float4*)&o[4];
    }
}

// ---------------- host ----------------
template <typename T>
static inline T* sym(const void* s) {
    void* p = nullptr;
    cudaGetSymbolAddress(&p, s);
    return (T*)p;
}

extern "C" void kernel_launch(void* const* d_in, const int* in_sizes, int n_in,
                              void* d_out, int out_size)
{
    const float* x    = (const float*)d_in[0];
    const int*   eraw = (const int*)  d_in[1];
    const float* istj = (const float*)d_in[2];
    const int base = (in_sizes[3] < 1000) ? 4 : 3;
    const float* W_go1 = (const float*)d_in[base + 0];
    const float* b_go1 = (const float*)d_in[base + 1];
    const float* W_go2 = (const float*)d_in[base + 2];
    const float* b_go2 = (const float*)d_in[base + 3];
    const float* W_c1  = (const float*)d_in[base + 4];
    const float* b_c1  = (const float*)d_in[base + 5];
    const float* W_c2  = (const float*)d_in[base + 6];
    const float* b_c2  = (const float*)d_in[base + 7];
    const float* W_r1  = (const float*)d_in[base + 8];
    const float* b_r1  = (const float*)d_in[base + 9];
    const float* W_r2  = (const float*)d_in[base + 10];
    const float* b_r2  = (const float*)d_in[base + 11];
    const float* W_f   = (const float*)d_in[base + 12];
    const float* b_f   = (const float*)d_in[base + 13];
    float* out = (float*)d_out;

    static cudaStream_t sA = nullptr, sB = nullptr;
    static cudaEvent_t eFork = nullptr, eGene = nullptr, eTop = nullptr, eJoin = nullptr;
    if (!sA) {
        cudaStreamCreateWithFlags(&sA, cudaStreamNonBlocking);
        cudaStreamCreateWithFlags(&sB, cudaStreamNonBlocking);
        cudaEventCreateWithFlags(&eFork, cudaEventDisableTiming);
        cudaEventCreateWithFlags(&eGene, cudaEventDisableTiming);
        cudaEventCreateWithFlags(&eTop,  cudaEventDisableTiming);
        cudaEventCreateWithFlags(&eJoin, cudaEventDisableTiming);
        cudaFuncSetAttribute((const void*)k_hgemm<false, true, true >,
                             cudaFuncAttributeMaxDynamicSharedMemorySize, GEMM_SMEM);
        cudaFuncSetAttribute((const void*)k_hgemm<true,  true, false>,
                             cudaFuncAttributeMaxDynamicSharedMemorySize, GEMM_SMEM);
    }

    __half* hw16 = sym<__half>(g_hw16);
    float* p_r1 = sym<float>(g_r1);
    float* p_r2 = sym<float>(g_r2);
    __half* xgo  = sym<__half>(g_xgo);
    __half* go1  = sym<__half>(g_go1);
    __half* xt   = sym<__half>(g_xt);
    __half* h1   = sym<__half>(g_h1);
    __half* wgo1 = sym<__half>(g_Wgo1T);
    __half* wgo2 = sym<__half>(g_Wgo2T);
    __half* w1   = sym<__half>(g_W1T);
    __half* w2   = sym<__half>(g_W2T);

    // ---- fork from the (captured) null stream ----
    cudaEventRecord(eFork, 0);
    cudaStreamWaitEvent(sA, eFork, 0);
    cudaStreamWaitEvent(sB, eFork, 0);

    // ======== stream B: goid MLP chain + layer1-top ========
    {
        dim3 b(32, 8);
        k_cvt_wT<<<dim3(1024 / 32, 4096 / 32), b, 0, sB>>>(W_go1, wgo1, 4096, 1024);
        k_cvt_wT<<<dim3(512 / 32, 1024 / 32),  b, 0, sB>>>(W_go2, wgo2, 1024, 512);
    }
    {
        size_t n2 = (size_t)MPAD_GO * GOIDD / 2;
        k_cvt_xgo<<<(unsigned)((n2 + 255) / 256), 256, 0, sB>>>(x);
    }
    k_zero16<<<(112 * 1024 / 2 + 255) / 256, 256, 0, sB>>>(go1 + (size_t)NGO * 1024, 112 * 1024 / 2);
    {
        dim3 g(1024 / 128, MPAD_GO / 128);
        k_hgemm<false, true, true><<<g, 256, GEMM_SMEM, sB>>>(
            xgo, wgo1, b_go1, go1, nullptr, NGO, 1024, 4096);
    }
    {
        dim3 g(512 / 128, MPAD_GO / 128);
        k_hgemm<false, true, true><<<g, 256, GEMM_SMEM, sB>>>(
            go1, wgo2, b_go2, xt + (size_t)NGENE * DIM, nullptr, NGO, 512, 1024);
    }

    // ======== stream A: graph preproc + gene conversion + layer1-bottom ========
    k_init_indeg<<<(NNODES + 255) / 256, 256, 0, sA>>>();
    k_detect_idx_dtype<<<1, 1024, 0, sA>>>(eraw);
    k_convert_edges<<<(NEDGES + 255) / 256, 256, 0, sA>>>(eraw);
    k_dinv<<<(NNODES + 255) / 256, 256, 0, sA>>>();
    k_scan1<<<NSCANB, 256, 0, sA>>>();
    k_scan2<<<1, 256, 0, sA>>>();
    k_scan3<<<NSCANB, 256, 0, sA>>>();
    k_fill_csr<<<(NEDGES + 255) / 256, 256, 0, sA>>>();
    k_cvt_gene<<<(unsigned)(((size_t)NGENE * DIM / 2 + 255) / 256), 256, 0, sA>>>(x);
    {
        dim3 b(32, 8);
        k_cvt_wT<<<dim3(512 / 32, 512 / 32), b, 0, sA>>>(W_c1, w1,             512, 512);
        k_cvt_wT<<<dim3(512 / 32, 512 / 32), b, 0, sA>>>(W_r1, w1 + 512 * 512, 512, 512);
        k_cvt_wT<<<dim3(256 / 32, 512 / 32), b, 0, sA>>>(W_c2, w2,             512, 256);
        k_cvt_wT<<<dim3(256 / 32, 512 / 32), b, 0, sA>>>(W_r2, w2 + 256 * 512, 512, 256);
    }
    k_zero16<<<(48 * 512 / 2 + 255) / 256, 256, 0, sA>>>(xt + (size_t)NNODES * DIM, 48 * 512 / 2);
    k_zero16<<<(48 * 512 / 2 + 255) / 256, 256, 0, sA>>>(h1 + (size_t)NNODES * DIM, 48 * 512 / 2);
    cudaEventRecord(eGene, sA);

    // layer1-bottom: rows [0, 39936) — pure gene data
    {
        dim3 g(1024 / 128, NROWS_BOT / 128);
        k_hgemm<true, true, false><<<g, 256, GEMM_SMEM, sA>>>(
            xt, w1, b_r1, hw16, p_r1, NROWS_BOT, 1024, 512);
    }

    // layer1-top on stream B: rows [39936, 50048)
    cudaStreamWaitEvent(sB, eGene, 0);
    {
        dim3 g(1024 / 128, NROWS_TOP / 128);
        k_hgemm<true, true, false><<<g, 256, GEMM_SMEM, sB>>>(
            xt   + (size_t)NROWS_BOT * DIM,
            w1, b_r1,
            hw16 + (size_t)NROWS_BOT * DIM,
            p_r1 + (size_t)NROWS_BOT * DIM,
            NNODES - NROWS_BOT, 1024, 512);
    }
    cudaEventRecord(eTop, sB);

    // ======== stream A continues: gathers + layer2 + fused fusion ========
    cudaStreamWaitEvent(sA, eTop, 0);
    k_gather_epi<DIM, true, false><<<NNODES, DIM / 8, 0, sA>>>(
        hw16, p_r1, b_c1, h1, nullptr, nullptr, nullptr, nullptr, nullptr);
    {
        dim3 g(512 / 128, MPAD_N / 128);
        k_hgemm<true, true, false><<<g, 256, GEMM_SMEM, sA>>>(
            h1, w2, b_r2, hw16, p_r2, NNODES, 512, 512);
    }
    // gather2 fused with fusion head, gene nodes only
    k_gather_epi<HID2D, false, true><<<NGENE, HID2D / 8, 0, sA>>>(
        hw16, p_r2, b_c2, nullptr, nullptr, istj, W_f, b_f, out);

    // ---- join back to the null stream ----
    cudaEventRecord(eJoin, sA);
    cudaStreamWaitEvent(0, eJoin, 0);

    (void)n_in; (void)out_size;
}

// round 14
// speedup vs baseline: 1.5736x; 1.0333x over previous
#include <cuda_runtime.h>
#include <cuda_fp16.h>
#include <cstdint>

// ---------------- problem constants ----------------
#define NNODES 50000
#define NGENE  40000
#define NGO    10000
#define NEDGES 800000
#define DIM    512
#define HID2D  256
#define GOIDD  4096
#define MPAD_GO 10112   // 79*128
#define MPAD_N  50048   // 391*128
#define NROWS_BOT 39936 // 312*128
#define NROWS_TOP 10112 // 79*128
#define NSCANB 196      // ceil(50000/256)

// ---------------- helpers ----------------
__device__ __forceinline__ uint32_t smem_u32(const void* p) {
    uint32_t a;
    asm("{ .reg .u64 t; cvta.to.shared.u64 t, %1; cvt.u32.u64 %0, t; }" : "=r"(a) : "l"(p));
    return a;
}
__device__ __forceinline__ void cp16(uint32_t d, const void* s) {
    asm volatile("cp.async.cg.shared.global [%0], [%1], 16;" :: "r"(d), "l"(s) : "memory");
}
#define CP_COMMIT() asm volatile("cp.async.commit_group;" ::: "memory")
#define CP_WAIT(n)  asm volatile("cp.async.wait_group %0;" :: "n"(n) : "memory")

__device__ __forceinline__ void ldsm4(uint32_t* r, uint32_t addr) {
    asm volatile("ldmatrix.sync.aligned.m8n8.x4.shared.b16 {%0,%1,%2,%3}, [%4];"
        : "=r"(r[0]), "=r"(r[1]), "=r"(r[2]), "=r"(r[3]) : "r"(addr));
}
__device__ __forceinline__ void mma16816(float* d, const uint32_t* a, const uint32_t* b) {
    asm volatile(
        "mma.sync.aligned.m16n8k16.row.col.f32.f16.f16.f32 "
        "{%0,%1,%2,%3}, {%4,%5,%6,%7}, {%8,%9}, {%0,%1,%2,%3};"
        : "+f"(d[0]), "+f"(d[1]), "+f"(d[2]), "+f"(d[3])
        : "r"(a[0]), "r"(a[1]), "r"(a[2]), "r"(a[3]), "r"(b[0]), "r"(b[1]));
}
__device__ __forceinline__ uint32_t swz(uint32_t base, uint32_t off) {
    return base + (off ^ ((off >> 3) & 0x70));
}
__device__ __forceinline__ void acc8(float* a, uint4 r, float w) {
    float2 f;
    f = __half22float2(*(const __half2*)&r.x); a[0] += w * f.x; a[1] += w * f.y;
    f = __half22float2(*(const __half2*)&r.y); a[2] += w * f.x; a[3] += w * f.y;
    f = __half22float2(*(const __half2*)&r.z); a[4] += w * f.x; a[5] += w * f.y;
    f = __half22float2(*(const __half2*)&r.w); a[6] += w * f.x; a[7] += w * f.y;
}
__device__ __forceinline__ void unpack8(float* o, uint4 r) {
    float2 f;
    f = __half22float2(*(const __half2*)&r.x); o[0] = f.x; o[1] = f.y;
    f = __half22float2(*(const __half2*)&r.y); o[2] = f.x; o[3] = f.y;
    f = __half22float2(*(const __half2*)&r.z); o[4] = f.x; o[5] = f.y;
    f = __half22float2(*(const __half2*)&r.w); o[6] = f.x; o[7] = f.y;
}

// ---------------- scratch (device globals) ----------------
__device__ int   g_is64;
__device__ int   g_src[NEDGES];
__device__ int   g_dst[NEDGES];
__device__ int   g_indeg[NNODES];
__device__ int   g_rowptr[NNODES + 1];
__device__ int   g_cursor[NNODES];
__device__ int   g_bsum[256];
__device__ float g_dinv[NNODES];
__device__ __align__(128) int2 g_csr[NEDGES];        // {src, w as int bits}

__device__ __align__(128) __half g_hw16[(size_t)NNODES * DIM];  // conv messages (fp16)
__device__ __align__(128) __half g_r1[(size_t)NNODES * DIM];    // residual 1 (fp16)
__device__ __align__(128) __half g_r2[(size_t)NNODES * HID2D];  // residual 2 (fp16)

// fp16 activations (rows padded to 128 multiples)
__device__ __align__(128) __half g_xgo[(size_t)MPAD_GO * GOIDD];
__device__ __align__(128) __half g_go1[(size_t)MPAD_GO * 1024];
__device__ __align__(128) __half g_xt [(size_t)MPAD_N * DIM];
__device__ __align__(128) __half g_h1 [(size_t)MPAD_N * DIM];

// fp16 transposed weights ([N,K] K-major)
__device__ __align__(128) __half g_Wgo1T[1024 * 4096];
__device__ __align__(128) __half g_Wgo2T[512 * 1024];
__device__ __align__(128) __half g_W1T[1024 * 512];   // [Wc1T ; Wr1T]
__device__ __align__(128) __half g_W2T[512 * 512];    // [Wc2T ; Wr2T]

// ---------------- graph preprocessing ----------------
__global__ void k_init_indeg() {
    int i = blockIdx.x * blockDim.x + threadIdx.x;
    if (i < NNODES) g_indeg[i] = 0;
}
__global__ void k_detect_idx_dtype(const int* __restrict__ raw) {
    __shared__ int flag;
    if (threadIdx.x == 0) flag = 1;
    __syncthreads();
    if (raw[2 * threadIdx.x + 1] != 0) flag = 0;
    __syncthreads();
    if (threadIdx.x == 0) g_is64 = flag;
}
__global__ void k_convert_edges(const int* __restrict__ raw) {
    int e = blockIdx.x * blockDim.x + threadIdx.x;
    if (e >= NEDGES) return;
    int s, d;
    if (g_is64) {
        const long long* r64 = (const long long*)raw;
        s = (int)r64[e]; d = (int)r64[NEDGES + e];
    } else {
        s = raw[e]; d = raw[NEDGES + e];
    }
    g_src[e] = s; g_dst[e] = d;
    atomicAdd(&g_indeg[d], 1);
}
__global__ void k_dinv() {
    int i = blockIdx.x * blockDim.x + threadIdx.x;
    if (i < NNODES) g_dinv[i] = rsqrtf(1.0f + (float)g_indeg[i]);
}
__global__ void k_scan1() {
    __shared__ int sh[256];
    const int b = blockIdx.x, t = threadIdx.x;
    const int i = b * 256 + t;
    int v = (i < NNODES) ? g_indeg[i] : 0;
    sh[t] = v;
    __syncthreads();
#pragma unroll
    for (int off = 1; off < 256; off <<= 1) {
        int x = (t >= off) ? sh[t - off] : 0;
        __syncthreads();
        sh[t] += x;
        __syncthreads();
    }
    if (i < NNODES) g_rowptr[i] = sh[t] - v;
    if (t == 255) g_bsum[b] = sh[255];
}
__global__ void k_scan2() {
    __shared__ int sh[256];
    const int t = threadIdx.x;
    int v = (t < NSCANB) ? g_bsum[t] : 0;
    sh[t] = v;
    __syncthreads();
#pragma unroll
    for (int off = 1; off < 256; off <<= 1) {
        int x = (t >= off) ? sh[t - off] : 0;
        __syncthreads();
        sh[t] += x;
        __syncthreads();
    }
    if (t < NSCANB) g_bsum[t] = sh[t] - v;
    if (t == 255) g_rowptr[NNODES] = sh[255];
}
__global__ void k_scan3() {
    const int b = blockIdx.x, t = threadIdx.x;
    const int i = b * 256 + t;
    if (i < NNODES) {
        int r = g_rowptr[i] + g_bsum[b];
        g_rowptr[i] = r;
        g_cursor[i] = r;
    }
}
__global__ void k_fill_csr() {
    int e = blockIdx.x * blockDim.x + threadIdx.x;
    if (e >= NEDGES) return;
    int s = g_src[e], d = g_dst[e];
    int p = atomicAdd(&g_cursor[d], 1);
    g_csr[p] = make_int2(s, __float_as_int(g_dinv[s] * g_dinv[d]));
}

// ---------------- conversion kernels ----------------
__global__ void k_cvt_xgo(const float* __restrict__ x) {
    size_t i = (size_t)blockIdx.x * blockDim.x + threadIdx.x;
    const size_t total = (size_t)MPAD_GO * GOIDD / 2;
    if (i >= total) return;
    size_t row = i / (GOIDD / 2), c2 = i % (GOIDD / 2);
    float2 v = make_float2(0.f, 0.f);
    if (row < NGO) v = ((const float2*)x)[((size_t)(NGENE + row) * GOIDD) / 2 + c2];
    ((__half2*)g_xgo)[i] = __floats2half2_rn(v.x, v.y);
}
__global__ void k_cvt_gene(const float* __restrict__ x) {
    size_t i = (size_t)blockIdx.x * blockDim.x + threadIdx.x;
    const size_t total = (size_t)NGENE * DIM / 2;
    if (i >= total) return;
    size_t row = i / (DIM / 2), c2 = i % (DIM / 2);
    float2 v = ((const float2*)x)[((size_t)row * GOIDD) / 2 + c2];
    ((__half2*)g_xt)[(size_t)row * (DIM / 2) + c2] = __floats2half2_rn(v.x, v.y);
}
__global__ void k_cvt_wT(const float* __restrict__ W, __half* __restrict__ dh,
                         int K, int N) {
    __shared__ float tile[32][33];
    const int nb = blockIdx.x * 32, kb = blockIdx.y * 32;
    const int tx = threadIdx.x, ty = threadIdx.y;
#pragma unroll
    for (int r = 0; r < 32; r += 8)
        tile[ty + r][tx] = W[(size_t)(kb + ty + r) * N + nb + tx];
    __syncthreads();
#pragma unroll
    for (int r = 0; r < 32; r += 8) {
        float v = tile[tx][ty + r];
        dh[(size_t)(nb + ty + r) * K + kb + tx] = __float2half_rn(v);
    }
}
__global__ void k_zero16(__half* p, int n2) {
    int i = blockIdx.x * blockDim.x + threadIdx.x;
    if (i < n2) ((uint32_t*)p)[i] = 0u;
}

// ---------------- fp16 HMMA GEMM (single weight product) ----------------
// DUAL: cols [0,N/2) -> Ch fp16 (conv, no bias); cols [N/2,N) -> Cr fp16 (+bias).
#define GEMM_SMEM (3 * 2 * 16384)   // 96 KB

template <bool DUAL, bool BIAS, bool RELU>
__global__ __launch_bounds__(256, 2)
void k_hgemm(const __half* __restrict__ A, const __half* __restrict__ B,
             const float* __restrict__ bias,
             __half* __restrict__ Ch, __half* __restrict__ Cr,
             int M, int N, int K)
{
    extern __shared__ char smem[];
    const uint32_t sb = smem_u32(smem);
    const int tid  = threadIdx.x;
    const int wid  = tid >> 5;
    const int lane = tid & 31;
    const int wm   = wid >> 1;
    const int wn   = wid & 1;
    const int bm = blockIdx.y * 128, bn = blockIdx.x * 128;

    const uint32_t STAGE = 2 * 16384;

    const int lrow  = tid >> 1;
    const int lhalf = (tid & 1) * 64;
    const char* srcA = (const char*)(A + (size_t)(bm + lrow) * K) + lhalf;
    const char* srcB = (const char*)(B + (size_t)(bn + lrow) * K) + lhalf;

    const int NC = K / 64;

    auto load_chunk = [&](int s, int c) {
        const uint32_t kb = (uint32_t)c * 128;
        const uint32_t stg = sb + (uint32_t)s * STAGE;
        const uint32_t lbase = (uint32_t)lrow * 128 + (uint32_t)lhalf;
#pragma unroll
        for (int i = 0; i < 4; i++) {
            uint32_t off = lbase + i * 16;
            cp16(swz(stg, off),         srcA + kb + i * 16);
            cp16(swz(stg + 16384, off), srcB + kb + i * 16);
        }
        CP_COMMIT();
    };

    float acc[64];
#pragma unroll
    for (int i = 0; i < 64; i++) acc[i] = 0.f;

    const uint32_t a_row  = (uint32_t)(wm * 32) + (lane & 15);
    const uint32_t a_ksel = (lane >> 4) << 4;
    const uint32_t b_row  = (uint32_t)(wn * 64) + (lane & 7) + ((lane >> 4) << 3);
    const uint32_t b_ksel = (lane & 8) ? 16u : 0u;

    load_chunk(0, 0);
    if (NC > 1) load_chunk(1, 1);

    for (int c = 0; c < NC; c++) {
        if (c + 2 < NC) load_chunk((c + 2) % 3, c + 2);
        if (c + 2 < NC)      { CP_WAIT(2); }
        else if (c + 1 < NC) { CP_WAIT(1); }
        else                 { CP_WAIT(0); }
        __syncthreads();

        const uint32_t stg = sb + (uint32_t)(c % 3) * STAGE;
        const uint32_t tA = stg;
        const uint32_t tB = stg + 16384;

#pragma unroll
        for (int ks = 0; ks < 4; ks++) {
            const uint32_t kb = (uint32_t)ks * 32;
            uint32_t a[8];
            ldsm4(&a[0], swz(tA, (a_row)      * 128 + kb + a_ksel));
            ldsm4(&a[4], swz(tA, (a_row + 16) * 128 + kb + a_ksel));
#pragma unroll
            for (int p = 0; p < 4; p++) {
                uint32_t b4[4];
                ldsm4(b4, swz(tB, (b_row + p * 16) * 128 + kb + b_ksel));
#pragma unroll
                for (int mt = 0; mt < 2; mt++) {
                    mma16816(&acc[(mt * 8 + 2 * p) * 4],     &a[mt * 4], &b4[0]);
                    mma16816(&acc[(mt * 8 + 2 * p + 1) * 4], &a[mt * 4], &b4[2]);
                }
            }
        }
        __syncthreads();
    }

    // ---- epilogue ----
    const int half  = N >> 1;
    const bool sec  = DUAL && (bn >= half);
    const int cbase = sec ? half : 0;
    const int cstr  = DUAL ? half : N;

#pragma unroll
    for (int mt = 0; mt < 2; mt++) {
#pragma unroll
        for (int nt = 0; nt < 8; nt++) {
            const float* d = &acc[(mt * 8 + nt) * 4];
            const int r0 = bm + wm * 32 + mt * 16 + (lane >> 2);
            const int r1 = r0 + 8;
            const int col = bn + wn * 64 + nt * 8 + 2 * (lane & 3);
            float2 v0 = make_float2(d[0], d[1]);
            float2 v1 = make_float2(d[2], d[3]);
            if (DUAL) {
                const int cc = col - cbase;
                if (sec) {
                    if (BIAS) {
                        float b0 = bias[cc], b1 = bias[cc + 1];
                        v0.x += b0; v0.y += b1; v1.x += b0; v1.y += b1;
                    }
                    if (r0 < M) *(__half2*)(Cr + (size_t)r0 * cstr + cc) = __floats2half2_rn(v0.x, v0.y);
                    if (r1 < M) *(__half2*)(Cr + (size_t)r1 * cstr + cc) = __floats2half2_rn(v1.x, v1.y);
                } else {
                    if (r0 < M) *(__half2*)(Ch + (size_t)r0 * cstr + cc) = __floats2half2_rn(v0.x, v0.y);
                    if (r1 < M) *(__half2*)(Ch + (size_t)r1 * cstr + cc) = __floats2half2_rn(v1.x, v1.y);
                }
            } else {
                if (BIAS) {
                    float b0 = bias[col], b1 = bias[col + 1];
                    v0.x += b0; v0.y += b1; v1.x += b0; v1.y += b1;
                }
                if (RELU) {
                    v0.x = fmaxf(v0.x, 0.f); v0.y = fmaxf(v0.y, 0.f);
                    v1.x = fmaxf(v1.x, 0.f); v1.y = fmaxf(v1.y, 0.f);
                }
                if (r0 < M) *(__half2*)(Ch + (size_t)r0 * N + col) = __floats2half2_rn(v0.x, v0.y);
                if (r1 < M) *(__half2*)(Ch + (size_t)r1 * N + col) = __floats2half2_rn(v1.x, v1.y);
            }
        }
    }
}

// ---------------- gather 1: h1 = fp16( relu(agg + self + bias) + r1 ) --------
// one node per block, blockDim = DIM/8 = 64, 16B/thread.
__global__ void k_gather1(const __half* __restrict__ hw, const __half* __restrict__ rin,
                          const float* __restrict__ bias, __half* __restrict__ oh)
{
    const int F = DIM, F8 = F / 8;
    const int i = blockIdx.x;
    const int t = threadIdx.x;
    const int beg = g_rowptr[i], end = g_rowptr[i + 1];
    const uint4* hw8 = (const uint4*)hw;

    float acc[8];
#pragma unroll
    for (int j = 0; j < 8; j++) acc[j] = 0.f;

    int e = beg;
    for (; e + 1 < end; e += 2) {
        int2 e0 = g_csr[e], e1 = g_csr[e + 1];
        uint4 ra = hw8[(size_t)e0.x * F8 + t];
        uint4 rb = hw8[(size_t)e1.x * F8 + t];
        acc8(acc, ra, __int_as_float(e0.y));
        acc8(acc, rb, __int_as_float(e1.y));
    }
    if (e < end) {
        int2 e0 = g_csr[e];
        acc8(acc, hw8[(size_t)e0.x * F8 + t], __int_as_float(e0.y));
    }

    const float dv = g_dinv[i];
    const float sn = dv * dv;
    float sv[8], rr[8], bb[8];
    unpack8(sv, hw8[(size_t)i * F8 + t]);
    unpack8(rr, ((const uint4*)(rin + (size_t)i * F))[t]);
    *(float4*)&bb[0] = ((const float4*)bias)[2 * t];
    *(float4*)&bb[4] = ((const float4*)bias)[2 * t + 1];

    uint4 pk;
    float o0 = fmaxf(acc[0] + sn * sv[0] + bb[0], 0.f) + rr[0];
    float o1 = fmaxf(acc[1] + sn * sv[1] + bb[1], 0.f) + rr[1];
    *(__half2*)&pk.x = __floats2half2_rn(o0, o1);
    o0 = fmaxf(acc[2] + sn * sv[2] + bb[2], 0.f) + rr[2];
    o1 = fmaxf(acc[3] + sn * sv[3] + bb[3], 0.f) + rr[3];
    *(__half2*)&pk.y = __floats2half2_rn(o0, o1);
    o0 = fmaxf(acc[4] + sn * sv[4] + bb[4], 0.f) + rr[4];
    o1 = fmaxf(acc[5] + sn * sv[5] + bb[5], 0.f) + rr[5];
    *(__half2*)&pk.z = __floats2half2_rn(o0, o1);
    o0 = fmaxf(acc[6] + sn * sv[6] + bb[6], 0.f) + rr[6];
    o1 = fmaxf(acc[7] + sn * sv[7] + bb[7], 0.f) + rr[7];
    *(__half2*)&pk.w = __floats2half2_rn(o0, o1);
    ((uint4*)(oh + (size_t)i * F))[t] = pk;
}

// ---------------- gather 2 fused with fusion head (gene nodes only) ----------
// 4 nodes per block (one warp each), blockDim = 128. F = HID2D = 256, F8 = 32.
__global__ void k_gather_fuse(const __half* __restrict__ hw, const __half* __restrict__ rin,
                              const float* __restrict__ bias,
                              const float* __restrict__ istj, const float* __restrict__ Wf,
                              const float* __restrict__ bf, float* __restrict__ out)
{
    const int F = HID2D, F8 = F / 8;  // 32
    const int lane = threadIdx.x & 31;
    const int i = blockIdx.x * 4 + (threadIdx.x >> 5);
    const int beg = g_rowptr[i], end = g_rowptr[i + 1];
    const uint4* hw8 = (const uint4*)hw;

    float acc[8];
#pragma unroll
    for (int j = 0; j < 8; j++) acc[j] = 0.f;

    int e = beg;
    for (; e + 1 < end; e += 2) {
        int2 e0 = g_csr[e], e1 = g_csr[e + 1];
        uint4 ra = hw8[(size_t)e0.x * F8 + lane];
        uint4 rb = hw8[(size_t)e1.x * F8 + lane];
        acc8(acc, ra, __int_as_float(e0.y));
        acc8(acc, rb, __int_as_float(e1.y));
    }
    if (e < end) {
        int2 e0 = g_csr[e];
        acc8(acc, hw8[(size_t)e0.x * F8 + lane], __int_as_float(e0.y));
    }

    const float dv = g_dinv[i];
    const float sn = dv * dv;
    float sv[8], rr[8], bb[8];
    unpack8(sv, hw8[(size_t)i * F8 + lane]);
    unpack8(rr, ((const uint4*)(rin + (size_t)i * F))[lane]);
    *(float4*)&bb[0] = ((const float4*)bias)[2 * lane];
    *(float4*)&bb[4] = ((const float4*)bias)[2 * lane + 1];

    float a0 = 0.f, a1 = 0.f;
#pragma unroll
    for (int j = 0; j < 8; j++) {
        float o = fmaxf(acc[j] + sn * sv[j] + bb[j], 0.f) + rr[j];
        int k = 8 * lane + j;
        a0 += o * Wf[2 * k];
        a1 += o * Wf[2 * k + 1];
    }
#pragma unroll
    for (int off = 16; off > 0; off >>= 1) {
        a0 += __shfl_down_sync(0xffffffffu, a0, off);
        a1 += __shfl_down_sync(0xffffffffu, a1, off);
    }
    if (lane == 0) {
        float tv = istj[i];
        out[2 * i + 0] = a0 + tv * Wf[2 * F + 0] + bf[0];
        out[2 * i + 1] = a1 + tv * Wf[2 * F + 1] + bf[1];
    }
}

// ---------------- host ----------------
template <typename T>
static inline T* sym(const void* s) {
    void* p = nullptr;
    cudaGetSymbolAddress(&p, s);
    return (T*)p;
}

extern "C" void kernel_launch(void* const* d_in, const int* in_sizes, int n_in,
                              void* d_out, int out_size)
{
    const float* x    = (const float*)d_in[0];
    const int*   eraw = (const int*)  d_in[1];
    const float* istj = (const float*)d_in[2];
    const int base = (in_sizes[3] < 1000) ? 4 : 3;
    const float* W_go1 = (const float*)d_in[base + 0];
    const float* b_go1 = (const float*)d_in[base + 1];
    const float* W_go2 = (const float*)d_in[base + 2];
    const float* b_go2 = (const float*)d_in[base + 3];
    const float* W_c1  = (const float*)d_in[base + 4];
    const float* b_c1  = (const float*)d_in[base + 5];
    const float* W_c2  = (const float*)d_in[base + 6];
    const float* b_c2  = (const float*)d_in[base + 7];
    const float* W_r1  = (const float*)d_in[base + 8];
    const float* b_r1  = (const float*)d_in[base + 9];
    const float* W_r2  = (const float*)d_in[base + 10];
    const float* b_r2  = (const float*)d_in[base + 11];
    const float* W_f   = (const float*)d_in[base + 12];
    const float* b_f   = (const float*)d_in[base + 13];
    float* out = (float*)d_out;

    static cudaStream_t sA = nullptr, sB = nullptr;
    static cudaEvent_t eFork = nullptr, eGene = nullptr, eTop = nullptr, eJoin = nullptr;
    if (!sA) {
        cudaStreamCreateWithFlags(&sA, cudaStreamNonBlocking);
        cudaStreamCreateWithFlags(&sB, cudaStreamNonBlocking);
        cudaEventCreateWithFlags(&eFork, cudaEventDisableTiming);
        cudaEventCreateWithFlags(&eGene, cudaEventDisableTiming);
        cudaEventCreateWithFlags(&eTop,  cudaEventDisableTiming);
        cudaEventCreateWithFlags(&eJoin, cudaEventDisableTiming);
        cudaFuncSetAttribute((const void*)k_hgemm<false, true, true >,
                             cudaFuncAttributeMaxDynamicSharedMemorySize, GEMM_SMEM);
        cudaFuncSetAttribute((const void*)k_hgemm<true,  true, false>,
                             cudaFuncAttributeMaxDynamicSharedMemorySize, GEMM_SMEM);
    }

    __half* hw16 = sym<__half>(g_hw16);
    __half* p_r1 = sym<__half>(g_r1);
    __half* p_r2 = sym<__half>(g_r2);
    __half* xgo  = sym<__half>(g_xgo);
    __half* go1  = sym<__half>(g_go1);
    __half* xt   = sym<__half>(g_xt);
    __half* h1   = sym<__half>(g_h1);
    __half* wgo1 = sym<__half>(g_Wgo1T);
    __half* wgo2 = sym<__half>(g_Wgo2T);
    __half* w1   = sym<__half>(g_W1T);
    __half* w2   = sym<__half>(g_W2T);

    // ---- fork from the (captured) null stream ----
    cudaEventRecord(eFork, 0);
    cudaStreamWaitEvent(sA, eFork, 0);
    cudaStreamWaitEvent(sB, eFork, 0);

    // ======== stream B: goid MLP chain + layer1-top ========
    {
        dim3 b(32, 8);
        k_cvt_wT<<<dim3(1024 / 32, 4096 / 32), b, 0, sB>>>(W_go1, wgo1, 4096, 1024);
        k_cvt_wT<<<dim3(512 / 32, 1024 / 32),  b, 0, sB>>>(W_go2, wgo2, 1024, 512);
    }
    {
        size_t n2 = (size_t)MPAD_GO * GOIDD / 2;
        k_cvt_xgo<<<(unsigned)((n2 + 255) / 256), 256, 0, sB>>>(x);
    }
    k_zero16<<<(112 * 1024 / 2 + 255) / 256, 256, 0, sB>>>(go1 + (size_t)NGO * 1024, 112 * 1024 / 2);
    {
        dim3 g(1024 / 128, MPAD_GO / 128);
        k_hgemm<false, true, true><<<g, 256, GEMM_SMEM, sB>>>(
            xgo, wgo1, b_go1, go1, nullptr, NGO, 1024, 4096);
    }
    {
        dim3 g(512 / 128, MPAD_GO / 128);
        k_hgemm<false, true, true><<<g, 256, GEMM_SMEM, sB>>>(
            go1, wgo2, b_go2, xt + (size_t)NGENE * DIM, nullptr, NGO, 512, 1024);
    }

    // ======== stream A: graph preproc + gene conversion + layer1-bottom ========
    k_init_indeg<<<(NNODES + 255) / 256, 256, 0, sA>>>();
    k_detect_idx_dtype<<<1, 1024, 0, sA>>>(eraw);
    k_convert_edges<<<(NEDGES + 255) / 256, 256, 0, sA>>>(eraw);
    k_dinv<<<(NNODES + 255) / 256, 256, 0, sA>>>();
    k_scan1<<<NSCANB, 256, 0, sA>>>();
    k_scan2<<<1, 256, 0, sA>>>();
    k_scan3<<<NSCANB, 256, 0, sA>>>();
    k_fill_csr<<<(NEDGES + 255) / 256, 256, 0, sA>>>();
    k_cvt_gene<<<(unsigned)(((size_t)NGENE * DIM / 2 + 255) / 256), 256, 0, sA>>>(x);
    {
        dim3 b(32, 8);
        k_cvt_wT<<<dim3(512 / 32, 512 / 32), b, 0, sA>>>(W_c1, w1,             512, 512);
        k_cvt_wT<<<dim3(512 / 32, 512 / 32), b, 0, sA>>>(W_r1, w1 + 512 * 512, 512, 512);
        k_cvt_wT<<<dim3(256 / 32, 512 / 32), b, 0, sA>>>(W_c2, w2,             512, 256);
        k_cvt_wT<<<dim3(256 / 32, 512 / 32), b, 0, sA>>>(W_r2, w2 + 256 * 512, 512, 256);
    }
    k_zero16<<<(48 * 512 / 2 + 255) / 256, 256, 0, sA>>>(xt + (size_t)NNODES * DIM, 48 * 512 / 2);
    k_zero16<<<(48 * 512 / 2 + 255) / 256, 256, 0, sA>>>(h1 + (size_t)NNODES * DIM, 48 * 512 / 2);
    cudaEventRecord(eGene, sA);

    // layer1-bottom: rows [0, 39936) — pure gene data
    {
        dim3 g(1024 / 128, NROWS_BOT / 128);
        k_hgemm<true, true, false><<<g, 256, GEMM_SMEM, sA>>>(
            xt, w1, b_r1, hw16, p_r1, NROWS_BOT, 1024, 512);
    }

    // layer1-top on stream B: rows [39936, 50048)
    cudaStreamWaitEvent(sB, eGene, 0);
    {
        dim3 g(1024 / 128, NROWS_TOP / 128);
        k_hgemm<true, true, false><<<g, 256, GEMM_SMEM, sB>>>(
            xt   + (size_t)NROWS_BOT * DIM,
            w1, b_r1,
            hw16 + (size_t)NROWS_BOT * DIM,
            p_r1 + (size_t)NROWS_BOT * DIM,
            NNODES - NROWS_BOT, 1024, 512);
    }
    cudaEventRecord(eTop, sB);

    // ======== stream A continues: gathers + layer2 + fused fusion ========
    cudaStreamWaitEvent(sA, eTop, 0);
    k_gather1<<<NNODES, DIM / 8, 0, sA>>>(hw16, p_r1, b_c1, h1);
    {
        dim3 g(512 / 128, MPAD_N / 128);
        k_hgemm<true, true, false><<<g, 256, GEMM_SMEM, sA>>>(
            h1, w2, b_r2, hw16, p_r2, NNODES, 512, 512);
    }
    k_gather_fuse<<<NGENE / 4, 128, 0, sA>>>(hw16, p_r2, b_c2, istj, W_f, b_f, out);

    // ---- join back to the null stream ----
    cudaEventRecord(eJoin, sA);
    cudaStreamWaitEvent(0, eJoin, 0);

    (void)n_in; (void)out_size;
}